// round 15
// baseline (speedup 1.0000x reference)
#include <cuda_runtime.h>
#include <cuda_fp16.h>

typedef unsigned int u32; typedef unsigned short u16;
#define NTHR 256

// dense f16 weight images, [kgroup][n][64B] layout (conflict-free, no padding)
__device__ __align__(16) unsigned char g_wimg[249856];

// image offsets / sizes
#define O_L0   0
#define O_L1   16384
#define O_L2   49152
#define O_L3A  81920
#define O_L3B  114688
#define O_L4   131072
#define O_L5   163840
#define O_L6   196608
#define O_L7   229376

// smem layout
#define S_ROT  0        // 4 x 32768 rotating buffers
#define S_L0   131072   // 16384
#define S_L3B  147456   // 16384
#define S_L7   163840   // 20480
#define S_ESM  184320   // 256 rows x 64 f16 slots = 32768
#define S_AUX  217088   // ~5392
#define SMEMSZ 222480

__device__ __forceinline__ u32 smaddr(const void* p) {
    u32 a; asm("{ .reg .u64 t; cvta.to.shared.u64 t, %1; cvt.u32.u64 %0, t; }" : "=r"(a) : "l"(p));
    return a;
}
__device__ __forceinline__ u32 pkh(float lo, float hi) {
    u32 r; asm("cvt.rn.f16x2.f32 %0, %1, %2;" : "=r"(r) : "f"(hi), "f"(lo)); return r;
}
__device__ __forceinline__ void mma16816(float* c, const u32* a, u32 b0, u32 b1) {
    asm volatile("mma.sync.aligned.m16n8k16.row.col.f32.f16.f16.f32 "
                 "{%0,%1,%2,%3},{%4,%5,%6,%7},{%8,%9},{%0,%1,%2,%3};"
                 : "+f"(c[0]), "+f"(c[1]), "+f"(c[2]), "+f"(c[3])
                 : "r"(a[0]), "r"(a[1]), "r"(a[2]), "r"(a[3]), "r"(b0), "r"(b1));
}
__device__ __forceinline__ void lds128(u32* v, u32 ad) {
    asm volatile("ld.shared.v4.b32 {%0,%1,%2,%3}, [%4];"
        : "=r"(v[0]), "=r"(v[1]), "=r"(v[2]), "=r"(v[3]) : "r"(ad));
}
__device__ __forceinline__ void cpa16(u32 d, const void* s) {
    asm volatile("cp.async.cg.shared.global [%0], [%1], 16;" :: "r"(d), "l"(s) : "memory");
}
#define CPC()  asm volatile("cp.async.commit_group;" ::: "memory")
#define CPW0() asm volatile("cp.async.wait_group 0;" ::: "memory")
#define CPW2() asm volatile("cp.async.wait_group 2;" ::: "memory")

__device__ __forceinline__ void copy_async(u32 dst, const unsigned char* src, int bytes, int tid) {
    for (int i = tid * 16; i < bytes; i += NTHR * 16) cpa16(dst + (u32)i, src + i);
    CPC();
}

// A fragment from f16 esm (64-slot rows, 128B stride): row base er0, slot base sb.
__device__ __forceinline__ void efrag16(u32 er0, int sb, int q2, u32* f) {
    u32 b = er0 + (u32)((sb + q2) * 2);
    asm volatile("ld.shared.b32 %0, [%1];" : "=r"(f[0]) : "r"(b));
    asm volatile("ld.shared.b32 %0, [%1];" : "=r"(f[1]) : "r"(b + 1024));
    asm volatile("ld.shared.b32 %0, [%1];" : "=r"(f[2]) : "r"(b + 16));
    asm volatile("ld.shared.b32 %0, [%1];" : "=r"(f[3]) : "r"(b + 1040));
}

// Dual-tile GEMM, dense images: B frag addr = base + g*GS + j*512 (j = n-tile).
// base includes per-thread nl*64 + q*16. XMODE: 0 = AF groups; 1 = 2 esm groups
// (2nd kf of last is zero -> skipped); 2 = 4 AF groups + dir group (aA only, g=4).
template <int MPG, int XMODE, int NT, int GS, bool INIT>
__device__ __forceinline__ void gemm_dual(
    float (&C0)[16][4], float (&C1)[16][4],
    const u32 (&AF0)[8][4], const u32 (&AF1)[8][4],
    u32 base, u32 e00, u32 e10, const u32* xd0, const u32* xd1, int q2)
{
    constexpr int NG = MPG + (XMODE == 1 ? 2 : (XMODE == 2 ? 1 : 0));
    constexpr int H = NT / 4;
    if (INIT) {
#pragma unroll
        for (int t = 0; t < NT; t++) {
            C0[t][0] = 0.f; C0[t][1] = 0.f; C0[t][2] = 0.f; C0[t][3] = 0.f;
            C1[t][0] = 0.f; C1[t][1] = 0.f; C1[t][2] = 0.f; C1[t][3] = 0.f;
        }
    }
#pragma unroll
    for (int g = 0; g < NG; g++) {
        u32 aA0[4], aB0[4], aA1[4], aB1[4];
        const bool haveB = (g < MPG) || (XMODE == 1 && g == MPG);
        if (g < MPG) {
#pragma unroll
            for (int r = 0; r < 4; r++) {
                aA0[r] = AF0[2*g][r];   aB0[r] = AF0[2*g+1][r];
                aA1[r] = AF1[2*g][r];   aB1[r] = AF1[2*g+1][r];
            }
        } else if (XMODE == 1) {
            int sb = 32 * (g - MPG);
            efrag16(e00, sb, q2, aA0);
            efrag16(e10, sb, q2, aA1);
            if (haveB) { efrag16(e00, sb + 16, q2, aB0); efrag16(e10, sb + 16, q2, aB1); }
        } else {
#pragma unroll
            for (int r = 0; r < 4; r++) { aA0[r] = xd0[r]; aA1[r] = xd1[r]; }
        }
        const u32 ga = base + (u32)g * (u32)GS;
#pragma unroll
        for (int h = 0; h < H; h++) {
            u32 V[4][4];
#pragma unroll
            for (int t = 0; t < 4; t++) lds128(V[t], ga + (u32)(4*h+t) * 512u);
#pragma unroll
            for (int t = 0; t < 4; t++) {
                mma16816(C0[4*h+t], aA0, V[t][0], V[t][1]);
                mma16816(C1[4*h+t], aA1, V[t][0], V[t][1]);
            }
            if (haveB) {
#pragma unroll
                for (int t = 0; t < 4; t++) {
                    mma16816(C0[4*h+t], aB0, V[t][2], V[t][3]);
                    mma16816(C1[4*h+t], aB1, V[t][2], V[t][3]);
                }
            }
        }
    }
}

template <bool RELU>
__device__ __forceinline__ void epi_std(float (&C)[16][4], u32 (&AF)[8][4],
                                        const float* bias, int q2)
{
#pragma unroll
    for (int kf = 0; kf < 8; kf++) {
        float2 bA = *(const float2*)(bias + 16 * kf + q2);
        float2 bB = *(const float2*)(bias + 16 * kf + 8 + q2);
        float f0 = C[2*kf][0] + bA.x, f1 = C[2*kf][1] + bA.y;
        float f2 = C[2*kf][2] + bA.x, f3 = C[2*kf][3] + bA.y;
        float g0 = C[2*kf+1][0] + bB.x, g1 = C[2*kf+1][1] + bB.y;
        float g2 = C[2*kf+1][2] + bB.x, g3 = C[2*kf+1][3] + bB.y;
        if (RELU) {
            f0 = fmaxf(f0, 0.f); f1 = fmaxf(f1, 0.f); f2 = fmaxf(f2, 0.f); f3 = fmaxf(f3, 0.f);
            g0 = fmaxf(g0, 0.f); g1 = fmaxf(g1, 0.f); g2 = fmaxf(g2, 0.f); g3 = fmaxf(g3, 0.f);
        }
        AF[kf][0] = pkh(f0, f1); AF[kf][1] = pkh(f2, f3);
        AF[kf][2] = pkh(g0, g1); AF[kf][3] = pkh(g2, g3);
    }
}

__device__ __forceinline__ void epi_dens(float (&C)[16][4], u32 (&AF)[8][4],
                                         const float* bias, const float* wcS,
                                         float bd0, float* out, long long base,
                                         int q2, int q, int r0)
{
    float d0 = 0.f, d1 = 0.f;
#pragma unroll
    for (int kf = 0; kf < 8; kf++) {
        float2 bA = *(const float2*)(bias + 16 * kf + q2);
        float2 bB = *(const float2*)(bias + 16 * kf + 8 + q2);
        float2 wA = *(const float2*)(wcS + 16 * kf + q2);
        float2 wB = *(const float2*)(wcS + 16 * kf + 8 + q2);
        float f0 = fmaxf(C[2*kf][0] + bA.x, 0.f), f1 = fmaxf(C[2*kf][1] + bA.y, 0.f);
        float f2 = fmaxf(C[2*kf][2] + bA.x, 0.f), f3 = fmaxf(C[2*kf][3] + bA.y, 0.f);
        float g0 = fmaxf(C[2*kf+1][0] + bB.x, 0.f), g1 = fmaxf(C[2*kf+1][1] + bB.y, 0.f);
        float g2 = fmaxf(C[2*kf+1][2] + bB.x, 0.f), g3 = fmaxf(C[2*kf+1][3] + bB.y, 0.f);
        d0 += f0 * wA.x + f1 * wA.y + g0 * wB.x + g1 * wB.y;
        d1 += f2 * wA.x + f3 * wA.y + g2 * wB.x + g3 * wB.y;
        AF[kf][0] = pkh(f0, f1); AF[kf][1] = pkh(f2, f3);
        AF[kf][2] = pkh(g0, g1); AF[kf][3] = pkh(g2, g3);
    }
    d0 += __shfl_xor_sync(0xffffffffu, d0, 1); d0 += __shfl_xor_sync(0xffffffffu, d0, 2);
    d1 += __shfl_xor_sync(0xffffffffu, d1, 1); d1 += __shfl_xor_sync(0xffffffffu, d1, 2);
    if (q == 0) {
        out[base + r0]     = fmaxf(d0 + bd0, 0.f);
        out[base + r0 + 8] = fmaxf(d1 + bd0, 0.f);
    }
}

__device__ __forceinline__ void epi_rgb(float (&C)[16][4], const float* bias,
                                        const float* wr2S, const float* br2S,
                                        float* out, long long obase,
                                        int q2, int q, int r0)
{
    float p00 = 0.f, p01 = 0.f, p02 = 0.f, p10 = 0.f, p11 = 0.f, p12 = 0.f;
#pragma unroll
    for (int nt = 0; nt < 8; nt++) {
        float2 b = *(const float2*)(bias + 8 * nt + q2);
        float f0 = fmaxf(C[nt][0] + b.x, 0.f), f1 = fmaxf(C[nt][1] + b.y, 0.f);
        float f2 = fmaxf(C[nt][2] + b.x, 0.f), f3 = fmaxf(C[nt][3] + b.y, 0.f);
        int p0 = 8 * nt + q2;
        const float* wA = wr2S + p0 * 3;
        const float* wB = wr2S + (p0 + 1) * 3;
        p00 += f0 * wA[0] + f1 * wB[0];
        p01 += f0 * wA[1] + f1 * wB[1];
        p02 += f0 * wA[2] + f1 * wB[2];
        p10 += f2 * wA[0] + f3 * wB[0];
        p11 += f2 * wA[1] + f3 * wB[1];
        p12 += f2 * wA[2] + f3 * wB[2];
    }
    p00 += __shfl_xor_sync(0xffffffffu, p00, 1); p00 += __shfl_xor_sync(0xffffffffu, p00, 2);
    p01 += __shfl_xor_sync(0xffffffffu, p01, 1); p01 += __shfl_xor_sync(0xffffffffu, p01, 2);
    p02 += __shfl_xor_sync(0xffffffffu, p02, 1); p02 += __shfl_xor_sync(0xffffffffu, p02, 2);
    p10 += __shfl_xor_sync(0xffffffffu, p10, 1); p10 += __shfl_xor_sync(0xffffffffu, p10, 2);
    p11 += __shfl_xor_sync(0xffffffffu, p11, 1); p11 += __shfl_xor_sync(0xffffffffu, p11, 2);
    p12 += __shfl_xor_sync(0xffffffffu, p12, 1); p12 += __shfl_xor_sync(0xffffffffu, p12, 2);
    if (q == 0) {
        long long o0 = obase + (long long)r0 * 3;
        long long o1 = obase + (long long)(r0 + 8) * 3;
        out[o0]     = 1.f / (1.f + expf(-(p00 + br2S[0])));
        out[o0 + 1] = 1.f / (1.f + expf(-(p01 + br2S[1])));
        out[o0 + 2] = 1.f / (1.f + expf(-(p02 + br2S[2])));
        out[o1]     = 1.f / (1.f + expf(-(p10 + br2S[0])));
        out[o1 + 1] = 1.f / (1.f + expf(-(p11 + br2S[1])));
        out[o1 + 2] = 1.f / (1.f + expf(-(p12 + br2S[2])));
    }
}

// ---- prep: fp32 W[k][n] -> dense f16 [g][n][32 slots], quad-interleaved groups ----
__global__ void prep_kernel(const float* w0, const float* w1, const float* w2, const float* w3,
                            const float* w4, const float* w5, const float* wd, const float* wr1)
{
    const float* srcs[9] = {w0, w1, w2, w3, w3, w4, w5, wd, wr1};
    const int Ksrc[9] = {39, 128, 128, 128, 39, 128, 128, 128, 143};
    const int rof[9]  = {0, 0, 0, 0, 128, 0, 0, 0, 0};
    const int Kslt[9] = {64, 128, 128, 128, 64, 128, 128, 128, 160};
    const int Nn[9]   = {128, 128, 128, 128, 128, 128, 128, 128, 64};
    const int wst[9]  = {128, 128, 128, 128, 128, 128, 128, 129, 64};
    const int cof[9]  = {0, 0, 0, 0, 0, 0, 0, 1, 0};
    const int off[9]  = {O_L0, O_L1, O_L2, O_L3A, O_L3B, O_L4, O_L5, O_L6, O_L7};
    int j = blockIdx.x;
    const float* src = srcs[j];
    int N = Nn[j], KS = Kslt[j], tot = N * KS;
    u16* img = (u16*)(g_wimg + off[j]);
    for (int idx = threadIdx.x; idx < tot; idx += blockDim.x) {
        int n = idx / KS, s = idx - n * KS;
        float v = (s < Ksrc[j]) ? __ldg(src + (size_t)(s + rof[j]) * wst[j] + cof[j] + n) : 0.f;
        int u = s & 31, g32 = s >> 5;
        int q = (u & 7) >> 1;
        int pos = q * 8 + ((u >> 4) & 1) * 4 + ((u >> 3) & 1) * 2 + (u & 1);
        img[(size_t)g32 * N * 32 + (size_t)n * 32 + pos] = __half_as_ushort(__float2half_rn(v));
    }
}

__global__ void __launch_bounds__(NTHR, 1) nerf_mma_kernel(
    const float* __restrict__ pts, const float* __restrict__ dirs,
    const float* __restrict__ b0, const float* __restrict__ b1,
    const float* __restrict__ b2, const float* __restrict__ b3,
    const float* __restrict__ b4, const float* __restrict__ b5,
    const float* __restrict__ bd, const float* __restrict__ br1,
    const float* __restrict__ wd, const float* __restrict__ wr2,
    const float* __restrict__ br2, float* __restrict__ out, int ntiles)
{
    extern __shared__ __align__(16) unsigned char sm[];
    u16* esmH = (u16*)(sm + S_ESM);
    float* aux  = (float*)(sm + S_AUX);
    float* biasS = aux;            // 8 x 128
    float* wcS   = aux + 1024;
    float* wr2S  = aux + 1152;
    float* br2S  = aux + 1344;
    const u32 smb = smaddr(sm);

    const int tid = threadIdx.x, lane = tid & 31, wid = tid >> 5;
    const int q  = lane & 3;
    const int q2 = 2 * q;
    const int r0 = 16 * wid + (lane >> 2);
    const int nl = lane >> 2;

    {
        const float* bp[8] = {b0, b1, b2, b3, b4, b5, bd + 1, br1};
#pragma unroll 1
        for (int l = 0; l < 8; l++) {
            int n = (l == 7) ? 64 : 128;
            for (int i = tid; i < n; i += NTHR) biasS[l * 128 + i] = __ldg(bp[l] + i);
        }
        for (int i = tid; i < 128; i += NTHR) wcS[i] = __ldg(wd + (size_t)i * 129);
        for (int i = tid; i < 192; i += NTHR) wr2S[i] = __ldg(wr2 + i);
        if (tid < 3) br2S[tid] = __ldg(br2 + tid);
        for (int i = tid; i < 256 * 32; i += NTHR) ((u32*)esmH)[i] = 0;   // zero esm
    }
    // statics once
    copy_async(smb + S_L0,  g_wimg + O_L0,  16384, tid);
    copy_async(smb + S_L3B, g_wimg + O_L3B, 16384, tid);
    copy_async(smb + S_L7,  g_wimg + O_L7,  20480, tid);
    CPW0();
    __syncthreads();
    // initial rotation fill: G(R0..R3)
    copy_async(smb + 0,     g_wimg + O_L1,  32768, tid);
    copy_async(smb + 32768, g_wimg + O_L2,  32768, tid);
    copy_async(smb + 65536, g_wimg + O_L3A, 32768, tid);
    copy_async(smb + 98304, g_wimg + O_L4,  32768, tid);

    float C0[16][4], C1[16][4];
    u32 AF0[8][4], AF1[8][4];
    const float bd0 = __ldg(bd);
    const long long NPTS = (long long)ntiles * 128;
    const int npairs = ntiles >> 1;

    const u32 tN = (u32)(nl * 64 + q * 16);
    const u32 e00 = smb + S_ESM + (u32)(r0 * 128);
    const u32 e10 = e00 + 16384u;
    int c = 0;   // rotation cursor (0 or 2)

    for (int pair = blockIdx.x; pair < npairs; pair += gridDim.x) {
        // ---- xyz harmonic embed (f16) for both tiles: 2 thr/pt, 2 passes ----
#pragma unroll 1
        for (int p2 = 0; p2 < 2; p2++) {
            int p = tid & 127, half = tid >> 7;
            const float* qp = pts + (((long long)(2 * pair + p2)) * 128 + p) * 3;
            float v0 = __ldg(qp), v1 = __ldg(qp + 1), v2 = __ldg(qp + 2);
            u16* er = esmH + (p2 * 128 + p) * 64;
            if (half == 0) {
                float fr = 1.f;
#pragma unroll
                for (int f = 0; f < 6; f++) {
                    float s, cc; sincosf(v0 * fr, &s, &cc);
                    er[f] = __half_as_ushort(__float2half_rn(s));
                    er[18 + f] = __half_as_ushort(__float2half_rn(cc));
                    fr *= 2.f;
                }
                fr = 1.f;
#pragma unroll
                for (int f = 0; f < 3; f++) {
                    float s, cc; sincosf(v2 * fr, &s, &cc);
                    er[12 + f] = __half_as_ushort(__float2half_rn(s));
                    er[30 + f] = __half_as_ushort(__float2half_rn(cc));
                    fr *= 2.f;
                }
                er[36] = __half_as_ushort(__float2half_rn(v0));
                er[37] = __half_as_ushort(__float2half_rn(v1));
                er[38] = __half_as_ushort(__float2half_rn(v2));
            } else {
                float fr = 1.f;
#pragma unroll
                for (int f = 0; f < 6; f++) {
                    float s, cc; sincosf(v1 * fr, &s, &cc);
                    er[6 + f] = __half_as_ushort(__float2half_rn(s));
                    er[24 + f] = __half_as_ushort(__float2half_rn(cc));
                    fr *= 2.f;
                }
                fr = 8.f;
#pragma unroll
                for (int f = 3; f < 6; f++) {
                    float s, cc; sincosf(v2 * fr, &s, &cc);
                    er[12 + f] = __half_as_ushort(__float2half_rn(s));
                    er[30 + f] = __half_as_ushort(__float2half_rn(cc));
                    fr *= 2.f;
                }
            }
        }
        CPW2();                 // R0(L1), R1(L2) complete (leaves R2,R3 pending)
        __syncthreads();        // B_e: embed + copies visible

        const u32 bad0 = smb + (u32)((c + 0) & 3) * 32768u;
        const u32 bad1 = smb + (u32)((c + 1) & 3) * 32768u;
        const u32 bad2 = smb + (u32)((c + 2) & 3) * 32768u;
        const u32 bad3 = smb + (u32)((c + 3) & 3) * 32768u;

        // L0 (static, xyz esm)
        gemm_dual<0, 1, 16, 8192, true>(C0, C1, AF0, AF1, smb + S_L0 + tN, e00, e10, 0, 0, q2);
        epi_std<true>(C0, AF0, biasS, q2);
        epi_std<true>(C1, AF1, biasS, q2);
        // L1
        gemm_dual<4, 0, 16, 8192, true>(C0, C1, AF0, AF1, bad0 + tN, 0, 0, 0, 0, q2);
        epi_std<true>(C0, AF0, biasS + 128, q2);
        epi_std<true>(C1, AF1, biasS + 128, q2);
        // L2
        gemm_dual<4, 0, 16, 8192, true>(C0, C1, AF0, AF1, bad1 + tN, 0, 0, 0, 0, q2);
        epi_std<true>(C0, AF0, biasS + 256, q2);
        epi_std<true>(C1, AF1, biasS + 256, q2);

        CPW0();                 // R2(L3a), R3(L4) complete
        __syncthreads();        // B1
        copy_async(bad0, g_wimg + O_L5, 32768, tid);
        copy_async(bad1, g_wimg + O_L6, 32768, tid);

        // L3a (feat half of skip) — C carries, no epilogue
        gemm_dual<4, 0, 16, 8192, true>(C0, C1, AF0, AF1, bad2 + tN, 0, 0, 0, 0, q2);
        // L3b (static xyz half, accumulate) + epilogue
        gemm_dual<0, 1, 16, 8192, false>(C0, C1, AF0, AF1, smb + S_L3B + tN, e00, e10, 0, 0, q2);
        epi_std<true>(C0, AF0, biasS + 384, q2);
        epi_std<true>(C1, AF1, biasS + 384, q2);
        // L4
        gemm_dual<4, 0, 16, 8192, true>(C0, C1, AF0, AF1, bad3 + tN, 0, 0, 0, 0, q2);
        epi_std<true>(C0, AF0, biasS + 512, q2);
        epi_std<true>(C1, AF1, biasS + 512, q2);

        CPW0();                 // R4(L5), R5(L6) complete
        __syncthreads();        // B2
        copy_async(bad2, g_wimg + O_L1, 32768, tid);   // next tile R0'
        copy_async(bad3, g_wimg + O_L2, 32768, tid);   // next tile R1'

        // L5 (+density heads)
        gemm_dual<4, 0, 16, 8192, true>(C0, C1, AF0, AF1, bad0 + tN, 0, 0, 0, 0, q2);
        {
            long long base0 = (long long)(2 * pair) * 128;
            epi_dens(C0, AF0, biasS + 640, wcS, bd0, out, base0,       q2, q, r0);
            epi_dens(C1, AF1, biasS + 640, wcS, bd0, out, base0 + 128, q2, q, r0);
        }
        // L6 (no relu)
        gemm_dual<4, 0, 16, 8192, true>(C0, C1, AF0, AF1, bad1 + tN, 0, 0, 0, 0, q2);
        epi_std<false>(C0, AF0, biasS + 768, q2);
        epi_std<false>(C1, AF1, biasS + 768, q2);

        __syncthreads();        // B3 (no wait needed before it)
        copy_async(bad0, g_wimg + O_L3A, 32768, tid);  // next tile R2'
        copy_async(bad1, g_wimg + O_L4, 32768, tid);   // next tile R3'

        // dir frags
        u32 xd0[4], xd1[4];
#pragma unroll 1
        for (int p2 = 0; p2 < 2; p2++) {
            const float* dp = dirs + (long long)(2 * pair + p2) * 3;
            float d[16];
#pragma unroll
            for (int cc2 = 0; cc2 < 3; cc2++) {
                float v = __ldg(dp + cc2);
                float s0, cc0, s1, cc1;
                sincosf(v, &s0, &cc0); sincosf(2.f * v, &s1, &cc1);
                d[2*cc2] = s0; d[2*cc2+1] = s1; d[6+2*cc2] = cc0; d[7+2*cc2] = cc1; d[12+cc2] = v;
            }
            d[15] = 0.f;
            u32 lo = pkh(d[q2], d[q2+1]);
            u32 hi = pkh(d[8+q2], d[9+q2]);
            u32* xd = (p2 == 0) ? xd0 : xd1;
            xd[0] = lo; xd[1] = lo; xd[2] = hi; xd[3] = hi;
        }

        // L7 (static, feat + dir, +rgb heads)
        gemm_dual<4, 2, 8, 4096, true>(C0, C1, AF0, AF1, smb + S_L7 + tN, 0, 0, xd0, xd1, q2);
        {
            long long pb0 = (long long)(2 * pair) * 128;
            epi_rgb(C0, biasS + 896, wr2S, br2S, out, NPTS + pb0 * 3,         q2, q, r0);
            epi_rgb(C1, biasS + 896, wr2S, br2S, out, NPTS + (pb0 + 128) * 3, q2, q, r0);
        }
        c = (c + 2) & 3;
    }
}

extern "C" void kernel_launch(void* const* d_in, const int* in_sizes, int n_in,
                              void* d_out, int out_size)
{
    const float* pts  = (const float*)d_in[0];
    const float* dirs = (const float*)d_in[1];
    const float *w0 = (const float*)d_in[2],  *b0 = (const float*)d_in[3];
    const float *w1 = (const float*)d_in[4],  *b1 = (const float*)d_in[5];
    const float *w2 = (const float*)d_in[6],  *b2 = (const float*)d_in[7];
    const float *w3 = (const float*)d_in[8],  *b3 = (const float*)d_in[9];
    const float *w4 = (const float*)d_in[10], *b4 = (const float*)d_in[11];
    const float *w5 = (const float*)d_in[12], *b5 = (const float*)d_in[13];
    const float *wd = (const float*)d_in[14], *bd = (const float*)d_in[15];
    const float *wr1 = (const float*)d_in[16], *br1 = (const float*)d_in[17];
    const float *wr2 = (const float*)d_in[18], *br2 = (const float*)d_in[19];
    float* out = (float*)d_out;

    int ntiles = in_sizes[1] / 3;   // rays
    int npairs = ntiles >> 1;
    int nsm = 0;
    cudaDeviceGetAttribute(&nsm, cudaDevAttrMultiProcessorCount, 0);
    if (nsm <= 0) nsm = 148;
    int grid = nsm < npairs ? nsm : npairs;

    cudaFuncSetAttribute(nerf_mma_kernel, cudaFuncAttributeMaxDynamicSharedMemorySize, SMEMSZ);

    prep_kernel<<<9, 512>>>(w0, w1, w2, w3, w4, w5, wd, wr1);
    nerf_mma_kernel<<<grid, NTHR, SMEMSZ>>>(pts, dirs, b0, b1, b2, b3, b4, b5,
                                            bd, br1, wd, wr2, br2, out, ntiles);
}

// round 16
// speedup vs baseline: 1.2115x; 1.2115x over previous
#include <cuda_runtime.h>
#include <cuda_fp16.h>

typedef unsigned int u32; typedef unsigned short u16;
#define NTHR 256
#define ES 52   // esm row stride (floats)

// f16 weight images: transposed Wt[n][k], 32-slot quad-interleaved v4 layout.
__device__ __align__(16) unsigned char g_wimg[307200];

__device__ __forceinline__ u32 smaddr(const void* p) {
    u32 a; asm("{ .reg .u64 t; cvta.to.shared.u64 t, %1; cvt.u32.u64 %0, t; }" : "=r"(a) : "l"(p));
    return a;
}
__device__ __forceinline__ u32 pkh(float lo, float hi) {
    u32 r; asm("cvt.rn.f16x2.f32 %0, %1, %2;" : "=r"(r) : "f"(hi), "f"(lo)); return r;
}
__device__ __forceinline__ u32 hadd2(u32 a, u32 b) {
    u32 r; asm("add.rn.f16x2 %0, %1, %2;" : "=r"(r) : "r"(a), "r"(b)); return r;
}
__device__ __forceinline__ u32 hmax2z(u32 a) {
    u32 r; asm("max.f16x2 %0, %1, %2;" : "=r"(r) : "r"(a), "r"(0u)); return r;
}
__device__ __forceinline__ void mma16816(float* c, const u32* a, u32 b0, u32 b1) {
    asm volatile("mma.sync.aligned.m16n8k16.row.col.f32.f16.f16.f32 "
                 "{%0,%1,%2,%3},{%4,%5,%6,%7},{%8,%9},{%0,%1,%2,%3};"
                 : "+f"(c[0]), "+f"(c[1]), "+f"(c[2]), "+f"(c[3])
                 : "r"(a[0]), "r"(a[1]), "r"(a[2]), "r"(a[3]), "r"(b0), "r"(b1));
}
__device__ __forceinline__ void lds128(u32* v, u32 ad) {
    asm volatile("ld.shared.v4.b32 {%0,%1,%2,%3}, [%4];"
        : "=r"(v[0]), "=r"(v[1]), "=r"(v[2]), "=r"(v[3]) : "r"(ad));
}
__device__ __forceinline__ void cpa16(u32 d, const void* s) {
    asm volatile("cp.async.cg.shared.global [%0], [%1], 16;" :: "r"(d), "l"(s) : "memory");
}
#define CPC() asm volatile("cp.async.commit_group;" ::: "memory")
#define CPW() asm volatile("cp.async.wait_group 0;" ::: "memory")

__device__ __forceinline__ void copy_async(u32 dst, const unsigned char* src, int bytes, int tid) {
    for (int i = tid * 16; i < bytes; i += NTHR * 16) cpa16(dst + (u32)i, src + i);
    CPC();
}

// Build an A fragment for kf at esm column base cb (fp32 smem -> f16x2 regs).
__device__ __forceinline__ void efrag(const float* er0, int cb, int q2, u32* f) {
    float2 a = *(const float2*)(er0 + cb + q2);
    float2 b = *(const float2*)(er0 + 8 * ES + cb + q2);
    float2 c = *(const float2*)(er0 + cb + q2 + 8);
    float2 d = *(const float2*)(er0 + 8 * ES + cb + q2 + 8);
    f[0] = pkh(a.x, a.y); f[1] = pkh(b.x, b.y);
    f[2] = pkh(c.x, c.y); f[3] = pkh(d.x, d.y);
}

// Dual-tile GEMM: two M=128 tiles share every loaded B fragment.
// XMODE: 0 = AF groups only (V double-buffered); 1 = +2 esm groups (last group's
// second kf is zero-padded -> skipped); 2 = +1 dir group (aA only).
template <int MPG, int XMODE, int NT, int STB>
__device__ __forceinline__ void gemm_dual(
    float (&C0)[16][4], float (&C1)[16][4],
    const u32 (&AF0)[8][4], const u32 (&AF1)[8][4],
    u32 base, const float* e00, const float* e10,
    const u32* xd0, const u32* xd1, int q2)
{
    constexpr int NG = MPG + (XMODE == 1 ? 2 : (XMODE == 2 ? 1 : 0));
    constexpr int H = NT / 4;
#pragma unroll
    for (int t = 0; t < NT; t++) {
        C0[t][0] = 0.f; C0[t][1] = 0.f; C0[t][2] = 0.f; C0[t][3] = 0.f;
        C1[t][0] = 0.f; C1[t][1] = 0.f; C1[t][2] = 0.f; C1[t][3] = 0.f;
    }
#pragma unroll
    for (int g = 0; g < NG; g++) {
        u32 aA0[4], aB0[4], aA1[4], aB1[4];
        const bool haveB = (g < MPG) || (XMODE == 1 && g == MPG);
        if (g < MPG) {
#pragma unroll
            for (int r = 0; r < 4; r++) {
                aA0[r] = AF0[2*g][r];   aB0[r] = AF0[2*g+1][r];
                aA1[r] = AF1[2*g][r];   aB1[r] = AF1[2*g+1][r];
            }
        } else if (XMODE == 1) {
            int cb = 32 * (g - MPG);
            efrag(e00, cb, q2, aA0);
            efrag(e10, cb, q2, aA1);
            if (haveB) { efrag(e00, cb + 16, q2, aB0); efrag(e10, cb + 16, q2, aB1); }
        } else {   // XMODE == 2: dir group, aA only
#pragma unroll
            for (int r = 0; r < 4; r++) { aA0[r] = xd0[r]; aA1[r] = xd1[r]; }
        }
        const u32 ga = base + (u32)g * 64u;

        if (XMODE == 0) {
            u32 V[2][4][4];
#pragma unroll
            for (int t = 0; t < 4; t++) lds128(V[0][t], ga + (u32)t * (8u * (u32)STB));
#pragma unroll
            for (int h = 0; h < H; h++) {
                if (h + 1 < H) {
#pragma unroll
                    for (int t = 0; t < 4; t++)
                        lds128(V[(h+1)&1][t], ga + (u32)(4*(h+1)+t) * (8u * (u32)STB));
                }
                const u32 (*v)[4] = V[h&1];
#pragma unroll
                for (int t = 0; t < 4; t++) {
                    mma16816(C0[4*h+t], aA0, v[t][0], v[t][1]);
                    mma16816(C1[4*h+t], aA1, v[t][0], v[t][1]);
                }
#pragma unroll
                for (int t = 0; t < 4; t++) {
                    mma16816(C0[4*h+t], aB0, v[t][2], v[t][3]);
                    mma16816(C1[4*h+t], aB1, v[t][2], v[t][3]);
                }
            }
        } else {
#pragma unroll
            for (int h = 0; h < H; h++) {
                u32 V[4][4];
#pragma unroll
                for (int t = 0; t < 4; t++)
                    lds128(V[t], ga + (u32)(4*h+t) * (8u * (u32)STB));
#pragma unroll
                for (int t = 0; t < 4; t++) {
                    mma16816(C0[4*h+t], aA0, V[t][0], V[t][1]);
                    mma16816(C1[4*h+t], aA1, V[t][0], V[t][1]);
                }
                if (haveB) {
#pragma unroll
                    for (int t = 0; t < 4; t++) {
                        mma16816(C0[4*h+t], aB0, V[t][2], V[t][3]);
                        mma16816(C1[4*h+t], aB1, V[t][2], V[t][3]);
                    }
                }
            }
        }
    }
}

// packed epilogue: C -> f16x2 pairs, + f16x2 bias, (relu), straight into AF
template <bool RELU>
__device__ __forceinline__ void epi_std(float (&C)[16][4], u32 (&AF)[8][4],
                                        const u32* bh, int q)
{
#pragma unroll
    for (int kf = 0; kf < 8; kf++) {
        u32 bA = bh[8 * kf + q];
        u32 bB = bh[8 * kf + 4 + q];
        u32 c0 = hadd2(pkh(C[2*kf][0],   C[2*kf][1]),   bA);
        u32 c1 = hadd2(pkh(C[2*kf][2],   C[2*kf][3]),   bA);
        u32 c2 = hadd2(pkh(C[2*kf+1][0], C[2*kf+1][1]), bB);
        u32 c3 = hadd2(pkh(C[2*kf+1][2], C[2*kf+1][3]), bB);
        if (RELU) { c0 = hmax2z(c0); c1 = hmax2z(c1); c2 = hmax2z(c2); c3 = hmax2z(c3); }
        AF[kf][0] = c0; AF[kf][1] = c1; AF[kf][2] = c2; AF[kf][3] = c3;
    }
}

// L5 epilogue with fused density head (fp32 path, fp32 bias)
__device__ __forceinline__ void epi_dens(float (&C)[16][4], u32 (&AF)[8][4],
                                         const float* bias, const float* wcS,
                                         float bd0, float* out, long long base,
                                         int q2, int q, int r0)
{
    float d0 = 0.f, d1 = 0.f;
#pragma unroll
    for (int kf = 0; kf < 8; kf++) {
        float2 bA = *(const float2*)(bias + 16 * kf + q2);
        float2 bB = *(const float2*)(bias + 16 * kf + 8 + q2);
        float2 wA = *(const float2*)(wcS + 16 * kf + q2);
        float2 wB = *(const float2*)(wcS + 16 * kf + 8 + q2);
        float f0 = fmaxf(C[2*kf][0] + bA.x, 0.f), f1 = fmaxf(C[2*kf][1] + bA.y, 0.f);
        float f2 = fmaxf(C[2*kf][2] + bA.x, 0.f), f3 = fmaxf(C[2*kf][3] + bA.y, 0.f);
        float g0 = fmaxf(C[2*kf+1][0] + bB.x, 0.f), g1 = fmaxf(C[2*kf+1][1] + bB.y, 0.f);
        float g2 = fmaxf(C[2*kf+1][2] + bB.x, 0.f), g3 = fmaxf(C[2*kf+1][3] + bB.y, 0.f);
        d0 += f0 * wA.x + f1 * wA.y + g0 * wB.x + g1 * wB.y;
        d1 += f2 * wA.x + f3 * wA.y + g2 * wB.x + g3 * wB.y;
        AF[kf][0] = pkh(f0, f1); AF[kf][1] = pkh(f2, f3);
        AF[kf][2] = pkh(g0, g1); AF[kf][3] = pkh(g2, g3);
    }
    d0 += __shfl_xor_sync(0xffffffffu, d0, 1); d0 += __shfl_xor_sync(0xffffffffu, d0, 2);
    d1 += __shfl_xor_sync(0xffffffffu, d1, 1); d1 += __shfl_xor_sync(0xffffffffu, d1, 2);
    if (q == 0) {
        out[base + r0]     = fmaxf(d0 + bd0, 0.f);
        out[base + r0 + 8] = fmaxf(d1 + bd0, 0.f);
    }
}

// L7 epilogue: relu + rgb head (wr2 + sigmoid) — fp32 path
__device__ __forceinline__ void epi_rgb(float (&C)[16][4], const float* bias,
                                        const float* wr2S, const float* br2S,
                                        float* out, long long obase,
                                        int q2, int q, int r0)
{
    float p00 = 0.f, p01 = 0.f, p02 = 0.f, p10 = 0.f, p11 = 0.f, p12 = 0.f;
#pragma unroll
    for (int nt = 0; nt < 8; nt++) {
        float2 b = *(const float2*)(bias + 8 * nt + q2);
        float f0 = fmaxf(C[nt][0] + b.x, 0.f), f1 = fmaxf(C[nt][1] + b.y, 0.f);
        float f2 = fmaxf(C[nt][2] + b.x, 0.f), f3 = fmaxf(C[nt][3] + b.y, 0.f);
        int p0 = 8 * nt + q2;
        const float* wA = wr2S + p0 * 3;
        const float* wB = wr2S + (p0 + 1) * 3;
        p00 += f0 * wA[0] + f1 * wB[0];
        p01 += f0 * wA[1] + f1 * wB[1];
        p02 += f0 * wA[2] + f1 * wB[2];
        p10 += f2 * wA[0] + f3 * wB[0];
        p11 += f2 * wA[1] + f3 * wB[1];
        p12 += f2 * wA[2] + f3 * wB[2];
    }
    p00 += __shfl_xor_sync(0xffffffffu, p00, 1); p00 += __shfl_xor_sync(0xffffffffu, p00, 2);
    p01 += __shfl_xor_sync(0xffffffffu, p01, 1); p01 += __shfl_xor_sync(0xffffffffu, p01, 2);
    p02 += __shfl_xor_sync(0xffffffffu, p02, 1); p02 += __shfl_xor_sync(0xffffffffu, p02, 2);
    p10 += __shfl_xor_sync(0xffffffffu, p10, 1); p10 += __shfl_xor_sync(0xffffffffu, p10, 2);
    p11 += __shfl_xor_sync(0xffffffffu, p11, 1); p11 += __shfl_xor_sync(0xffffffffu, p11, 2);
    p12 += __shfl_xor_sync(0xffffffffu, p12, 1); p12 += __shfl_xor_sync(0xffffffffu, p12, 2);
    if (q == 0) {
        long long o0 = obase + (long long)r0 * 3;
        long long o1 = obase + (long long)(r0 + 8) * 3;
        out[o0]     = 1.f / (1.f + expf(-(p00 + br2S[0])));
        out[o0 + 1] = 1.f / (1.f + expf(-(p01 + br2S[1])));
        out[o0 + 2] = 1.f / (1.f + expf(-(p02 + br2S[2])));
        out[o1]     = 1.f / (1.f + expf(-(p10 + br2S[0])));
        out[o1 + 1] = 1.f / (1.f + expf(-(p11 + br2S[1])));
        out[o1 + 2] = 1.f / (1.f + expf(-(p12 + br2S[2])));
    }
}

// ---- prep: fp32 W[k][n] -> f16 Wt[n][pos], 32-slot quad-interleaved layout ----
__global__ void prep_kernel(const float* w0, const float* w1, const float* w2, const float* w3,
                            const float* w4, const float* w5, const float* wd, const float* wr1)
{
    const float* srcs[8] = {w0, w1, w2, w3, w4, w5, wd, wr1};
    const int Ksrc[8] = {39, 128, 128, 167, 128, 128, 128, 143};
    const int Kslt[8] = {64, 128, 128, 192, 128, 128, 128, 160};
    const int Nn[8]   = {128, 128, 128, 128, 128, 128, 128, 64};
    const int STw[8]  = {96, 160, 160, 224, 160, 160, 160, 160};
    const int wst[8]  = {128, 128, 128, 128, 128, 128, 129, 64};
    const int cof[8]  = {0, 0, 0, 0, 0, 0, 1, 0};
    const int off[8]  = {0, 24576, 65536, 106496, 163840, 204800, 245760, 286720};
    int j = blockIdx.x;
    const float* src = srcs[j];
    int N = Nn[j], S = STw[j], KS = Kslt[j], tot = N * KS;
    u16* img = (u16*)(g_wimg + off[j]);
    for (int idx = threadIdx.x; idx < tot; idx += blockDim.x) {
        int n = idx / KS, s = idx - n * KS;
        float v = (s < Ksrc[j]) ? __ldg(src + (size_t)s * wst[j] + cof[j] + n) : 0.f;
        int u = s & 31, g32 = s >> 5;
        int q = (u & 7) >> 1;
        int pos = g32 * 32 + q * 8 + ((u >> 4) & 1) * 4 + ((u >> 3) & 1) * 2 + (u & 1);
        img[(size_t)n * S + pos] = __half_as_ushort(__float2half_rn(v));
    }
}

__global__ void __launch_bounds__(NTHR, 1) nerf_mma_kernel(
    const float* __restrict__ pts, const float* __restrict__ dirs,
    const float* __restrict__ b0, const float* __restrict__ b1,
    const float* __restrict__ b2, const float* __restrict__ b3,
    const float* __restrict__ b4, const float* __restrict__ b5,
    const float* __restrict__ bd, const float* __restrict__ br1,
    const float* __restrict__ wd, const float* __restrict__ wr2,
    const float* __restrict__ br2, float* __restrict__ out, int ntiles)
{
    extern __shared__ __align__(16) unsigned char sm[];
    unsigned char* wbuf0 = sm;                       // 69632  (even layers)
    unsigned char* wbuf1 = sm + 69632;               // 94208  (odd layers, incl L3)
    float* esm  = (float*)(sm + 163840);             // 256 x ES fp32 embed (2 tiles)
    float* aux  = (float*)(sm + 163840 + 256 * ES * 4);
    float* biasS = aux;                              // 8 x 128 fp32 (for dens/rgb epi)
    float* wcS   = aux + 1024;                       // wd col 0
    float* wr2S  = aux + 1152;                       // 64 x 3
    float* br2S  = aux + 1344;                       // 3
    u32*  biasH  = (u32*)(aux + 1348);               // 8 x 64 f16x2-packed biases
    const u32 wb0 = smaddr(wbuf0), wb1 = smaddr(wbuf1);

    const int tid = threadIdx.x, lane = tid & 31, wid = tid >> 5;
    const int q  = lane & 3;
    const int q2 = 2 * q;
    const int r0 = 16 * wid + (lane >> 2);
    const int nl = lane >> 2;

    {
        const float* bp[8] = {b0, b1, b2, b3, b4, b5, bd + 1, br1};
#pragma unroll 1
        for (int l = 0; l < 8; l++) {
            int n = (l == 7) ? 64 : 128;
            for (int i = tid; i < n; i += NTHR) biasS[l * 128 + i] = __ldg(bp[l] + i);
        }
        for (int i = tid; i < 128; i += NTHR) wcS[i] = __ldg(wd + (size_t)i * 129);
        for (int i = tid; i < 192; i += NTHR) wr2S[i] = __ldg(wr2 + i);
        if (tid < 3) br2S[tid] = __ldg(br2 + tid);
        // pack biases to f16x2: biasH[l*64 + kf*8 + half*4 + qq]
        for (int i = tid; i < 512; i += NTHR) {
            int l = i >> 6, rem = i & 63;
            int kf = rem >> 3, half = (rem >> 2) & 1, qq = rem & 3;
            int n0 = 16 * kf + 8 * half + 2 * qq;
            float v0 = 0.f, v1 = 0.f;
            int lim = (l == 7) ? 64 : 128;
            if (n0 < lim)     v0 = __ldg(bp[l] + n0);
            if (n0 + 1 < lim) v1 = __ldg(bp[l] + n0 + 1);
            biasH[i] = pkh(v0, v1);
        }
    }
    copy_async(wb0, g_wimg, 24576, tid);   // L0
    CPW();
    __syncthreads();

    float C0[16][4], C1[16][4];
    u32 AF0[8][4], AF1[8][4];
    const float bd0 = __ldg(bd);
    const long long NPTS = (long long)ntiles * 128;
    const int npairs = ntiles >> 1;

    const u32 t192 = (u32)(nl * 192 + q * 16);
    const u32 t320 = (u32)(nl * 320 + q * 16);
    const u32 t448 = (u32)(nl * 448 + q * 16);
    const float* e00 = esm + r0 * ES;
    const float* e10 = esm + (128 + r0) * ES;

    for (int pair = blockIdx.x; pair < npairs; pair += gridDim.x) {
        // ---- xyz harmonic embed for BOTH tiles (2 threads per point, 2 passes) ----
#pragma unroll 1
        for (int p2 = 0; p2 < 2; p2++) {
            int p = tid & 127, half = tid >> 7;
            const float* qp = pts + (((long long)(2 * pair + p2)) * 128 + p) * 3;
            float v0 = __ldg(qp), v1 = __ldg(qp + 1), v2 = __ldg(qp + 2);
            float* er = esm + (p2 * 128 + p) * ES;
            if (half == 0) {
                float fr = 1.f;
#pragma unroll
                for (int f = 0; f < 6; f++) {
                    float s, c; sincosf(v0 * fr, &s, &c);
                    er[f] = s; er[18 + f] = c; fr *= 2.f;
                }
                fr = 1.f;
#pragma unroll
                for (int f = 0; f < 3; f++) {
                    float s, c; sincosf(v2 * fr, &s, &c);
                    er[12 + f] = s; er[30 + f] = c; fr *= 2.f;
                }
                er[36] = v0; er[37] = v1; er[38] = v2;
#pragma unroll
                for (int i = 39; i < 48; i++) er[i] = 0.f;
            } else {
                float fr = 1.f;
#pragma unroll
                for (int f = 0; f < 6; f++) {
                    float s, c; sincosf(v1 * fr, &s, &c);
                    er[6 + f] = s; er[24 + f] = c; fr *= 2.f;
                }
                fr = 8.f;
#pragma unroll
                for (int f = 3; f < 6; f++) {
                    float s, c; sincosf(v2 * fr, &s, &c);
                    er[12 + f] = s; er[30 + f] = c; fr *= 2.f;
                }
            }
        }
        __syncthreads();

        // ---- L0 (xyz from esm, 2 extra groups, last kf skipped) ----
        copy_async(wb1, g_wimg + 24576, 40960, tid);
        gemm_dual<0, 1, 16, 192>(C0, C1, AF0, AF1, wb0 + t192, e00, e10, 0, 0, q2);
        epi_std<true>(C0, AF0, biasH, q);
        epi_std<true>(C1, AF1, biasH, q);
        CPW(); __syncthreads();

        // ---- L1 ----
        copy_async(wb0, g_wimg + 65536, 40960, tid);
        gemm_dual<4, 0, 16, 320>(C0, C1, AF0, AF1, wb1 + t320, 0, 0, 0, 0, q2);
        epi_std<true>(C0, AF0, biasH + 64, q);
        epi_std<true>(C1, AF1, biasH + 64, q);
        CPW(); __syncthreads();

        // ---- L2 ----
        copy_async(wb1, g_wimg + 106496, 57344, tid);
        gemm_dual<4, 0, 16, 320>(C0, C1, AF0, AF1, wb0 + t320, 0, 0, 0, 0, q2);
        epi_std<true>(C0, AF0, biasH + 128, q);
        epi_std<true>(C1, AF1, biasH + 128, q);
        CPW(); __syncthreads();

        // ---- L3 (skip concat: 4 AF groups + 2 esm groups) ----
        copy_async(wb0, g_wimg + 163840, 40960, tid);
        gemm_dual<4, 1, 16, 448>(C0, C1, AF0, AF1, wb1 + t448, e00, e10, 0, 0, q2);
        epi_std<true>(C0, AF0, biasH + 192, q);
        epi_std<true>(C1, AF1, biasH + 192, q);
        CPW(); __syncthreads();

        // ---- L4 ----
        copy_async(wb1, g_wimg + 204800, 40960, tid);
        gemm_dual<4, 0, 16, 320>(C0, C1, AF0, AF1, wb0 + t320, 0, 0, 0, 0, q2);
        epi_std<true>(C0, AF0, biasH + 256, q);
        epi_std<true>(C1, AF1, biasH + 256, q);
        CPW(); __syncthreads();

        // ---- L5 (+fused density heads, fp32 epilogue) ----
        copy_async(wb0, g_wimg + 245760, 40960, tid);
        gemm_dual<4, 0, 16, 320>(C0, C1, AF0, AF1, wb1 + t320, 0, 0, 0, 0, q2);
        {
            long long base0 = (long long)(2 * pair) * 128;
            epi_dens(C0, AF0, biasS + 640, wcS, bd0, out, base0,       q2, q, r0);
            epi_dens(C1, AF1, biasS + 640, wcS, bd0, out, base0 + 128, q2, q, r0);
        }
        CPW(); __syncthreads();

        // ---- L6 (wd cols 1..128, NO relu) ----
        copy_async(wb1, g_wimg + 286720, 20480, tid);
        gemm_dual<4, 0, 16, 320>(C0, C1, AF0, AF1, wb0 + t320, 0, 0, 0, 0, q2);
        epi_std<false>(C0, AF0, biasH + 384, q);
        epi_std<false>(C1, AF1, biasH + 384, q);
        CPW(); __syncthreads();

        // ---- dir frags for both tiles (4 regs each) ----
        u32 xd0[4], xd1[4];
#pragma unroll 1
        for (int p2 = 0; p2 < 2; p2++) {
            const float* dp = dirs + (long long)(2 * pair + p2) * 3;
            float d[16];
#pragma unroll
            for (int c = 0; c < 3; c++) {
                float v = __ldg(dp + c);
                float s0, cc0, s1, cc1;
                sincosf(v, &s0, &cc0); sincosf(2.f * v, &s1, &cc1);
                d[2*c] = s0; d[2*c+1] = s1; d[6+2*c] = cc0; d[7+2*c] = cc1; d[12+c] = v;
            }
            d[15] = 0.f;
            u32 lo = pkh(d[q2], d[q2+1]);
            u32 hi = pkh(d[8+q2], d[9+q2]);
            u32* xd = (p2 == 0) ? xd0 : xd1;
            xd[0] = lo; xd[1] = lo; xd[2] = hi; xd[3] = hi;
        }

        // ---- L7 (wr1 -> 64: 4 AF groups + dir group (aA only), +fused rgb heads) ----
        copy_async(wb0, g_wimg, 24576, tid);   // next pair's L0
        gemm_dual<4, 2, 8, 320>(C0, C1, AF0, AF1, wb1 + t320, 0, 0, xd0, xd1, q2);
        {
            long long pb0 = (long long)(2 * pair) * 128;
            epi_rgb(C0, biasS + 896, wr2S, br2S, out, NPTS + pb0 * 3,         q2, q, r0);
            epi_rgb(C1, biasS + 896, wr2S, br2S, out, NPTS + (pb0 + 128) * 3, q2, q, r0);
        }
        CPW(); __syncthreads();
    }
}

extern "C" void kernel_launch(void* const* d_in, const int* in_sizes, int n_in,
                              void* d_out, int out_size)
{
    const float* pts  = (const float*)d_in[0];
    const float* dirs = (const float*)d_in[1];
    const float *w0 = (const float*)d_in[2],  *b0 = (const float*)d_in[3];
    const float *w1 = (const float*)d_in[4],  *b1 = (const float*)d_in[5];
    const float *w2 = (const float*)d_in[6],  *b2 = (const float*)d_in[7];
    const float *w3 = (const float*)d_in[8],  *b3 = (const float*)d_in[9];
    const float *w4 = (const float*)d_in[10], *b4 = (const float*)d_in[11];
    const float *w5 = (const float*)d_in[12], *b5 = (const float*)d_in[13];
    const float *wd = (const float*)d_in[14], *bd = (const float*)d_in[15];
    const float *wr1 = (const float*)d_in[16], *br1 = (const float*)d_in[17];
    const float *wr2 = (const float*)d_in[18], *br2 = (const float*)d_in[19];
    float* out = (float*)d_out;

    int ntiles = in_sizes[1] / 3;   // rays
    int npairs = ntiles >> 1;
    int nsm = 0;
    cudaDeviceGetAttribute(&nsm, cudaDevAttrMultiProcessorCount, 0);
    if (nsm <= 0) nsm = 148;
    int grid = nsm < npairs ? nsm : npairs;

    size_t smem = 163840 + 256 * ES * 4 + 5392 + 2048;   // ~224560? no: 163840+53248+7440 = 224528
    cudaFuncSetAttribute(nerf_mma_kernel, cudaFuncAttributeMaxDynamicSharedMemorySize, (int)smem);

    prep_kernel<<<8, 512>>>(w0, w1, w2, w3, w4, w5, wd, wr1);
    nerf_mma_kernel<<<grid, NTHR, smem>>>(pts, dirs, b0, b1, b2, b3, b4, b5,
                                          bd, br1, wd, wr2, br2, out, ntiles);
}

// round 17
// speedup vs baseline: 1.3079x; 1.0795x over previous
#include <cuda_runtime.h>
#include <cuda_fp16.h>

typedef unsigned int u32; typedef unsigned short u16;
#define NTHR 256
#define ES 52   // esm row stride (floats)

// f16 weight images: transposed Wt[n][k], 32-slot quad-interleaved v4 layout.
__device__ __align__(16) unsigned char g_wimg[307200];

__device__ __forceinline__ u32 smaddr(const void* p) {
    u32 a; asm("{ .reg .u64 t; cvta.to.shared.u64 t, %1; cvt.u32.u64 %0, t; }" : "=r"(a) : "l"(p));
    return a;
}
__device__ __forceinline__ u32 pkh(float lo, float hi) {
    u32 r; asm("cvt.rn.f16x2.f32 %0, %1, %2;" : "=r"(r) : "f"(hi), "f"(lo)); return r;
}
__device__ __forceinline__ u32 hadd2(u32 a, u32 b) {
    u32 r; asm("add.rn.f16x2 %0, %1, %2;" : "=r"(r) : "r"(a), "r"(b)); return r;
}
__device__ __forceinline__ u32 hmax2z(u32 a) {
    u32 r; asm("max.f16x2 %0, %1, %2;" : "=r"(r) : "r"(a), "r"(0u)); return r;
}
__device__ __forceinline__ void mma16816(float* c, const u32* a, u32 b0, u32 b1) {
    asm volatile("mma.sync.aligned.m16n8k16.row.col.f32.f16.f16.f32 "
                 "{%0,%1,%2,%3},{%4,%5,%6,%7},{%8,%9},{%0,%1,%2,%3};"
                 : "+f"(c[0]), "+f"(c[1]), "+f"(c[2]), "+f"(c[3])
                 : "r"(a[0]), "r"(a[1]), "r"(a[2]), "r"(a[3]), "r"(b0), "r"(b1));
}
__device__ __forceinline__ void lds128(u32* v, u32 ad) {
    asm volatile("ld.shared.v4.b32 {%0,%1,%2,%3}, [%4];"
        : "=r"(v[0]), "=r"(v[1]), "=r"(v[2]), "=r"(v[3]) : "r"(ad));
}
__device__ __forceinline__ void cpa16(u32 d, const void* s) {
    asm volatile("cp.async.cg.shared.global [%0], [%1], 16;" :: "r"(d), "l"(s) : "memory");
}
#define CPC() asm volatile("cp.async.commit_group;" ::: "memory")
#define CPW() asm volatile("cp.async.wait_group 0;" ::: "memory")

__device__ __forceinline__ void copy_async(u32 dst, const unsigned char* src, int bytes, int tid) {
    for (int i = tid * 16; i < bytes; i += NTHR * 16) cpa16(dst + (u32)i, src + i);
    CPC();
}

// fast sincos via MUFU (inputs |x| <~ 200: reduction error << f16 rounding)
__device__ __forceinline__ void fsincos(float x, float* s, float* c) {
    *s = __sinf(x); *c = __cosf(x);
}

// Build an A fragment for kf at esm column base cb (fp32 smem -> f16x2 regs).
__device__ __forceinline__ void efrag(const float* er0, int cb, int q2, u32* f) {
    float2 a = *(const float2*)(er0 + cb + q2);
    float2 b = *(const float2*)(er0 + 8 * ES + cb + q2);
    float2 c = *(const float2*)(er0 + cb + q2 + 8);
    float2 d = *(const float2*)(er0 + 8 * ES + cb + q2 + 8);
    f[0] = pkh(a.x, a.y); f[1] = pkh(b.x, b.y);
    f[2] = pkh(c.x, c.y); f[3] = pkh(d.x, d.y);
}

// Dual-tile GEMM: two M=128 tiles share every loaded B fragment.
// XMODE: 0 = AF groups only (V double-buffered); 1 = +2 esm groups (last group's
// second kf is zero-padded -> skipped); 2 = +1 dir group (aA only).
template <int MPG, int XMODE, int NT, int STB>
__device__ __forceinline__ void gemm_dual(
    float (&C0)[16][4], float (&C1)[16][4],
    const u32 (&AF0)[8][4], const u32 (&AF1)[8][4],
    u32 base, const float* e00, const float* e10,
    const u32* xd0, const u32* xd1, int q2)
{
    constexpr int NG = MPG + (XMODE == 1 ? 2 : (XMODE == 2 ? 1 : 0));
    constexpr int H = NT / 4;
#pragma unroll
    for (int t = 0; t < NT; t++) {
        C0[t][0] = 0.f; C0[t][1] = 0.f; C0[t][2] = 0.f; C0[t][3] = 0.f;
        C1[t][0] = 0.f; C1[t][1] = 0.f; C1[t][2] = 0.f; C1[t][3] = 0.f;
    }
#pragma unroll
    for (int g = 0; g < NG; g++) {
        u32 aA0[4], aB0[4], aA1[4], aB1[4];
        const bool haveB = (g < MPG) || (XMODE == 1 && g == MPG);
        if (g < MPG) {
#pragma unroll
            for (int r = 0; r < 4; r++) {
                aA0[r] = AF0[2*g][r];   aB0[r] = AF0[2*g+1][r];
                aA1[r] = AF1[2*g][r];   aB1[r] = AF1[2*g+1][r];
            }
        } else if (XMODE == 1) {
            int cb = 32 * (g - MPG);
            efrag(e00, cb, q2, aA0);
            efrag(e10, cb, q2, aA1);
            if (haveB) { efrag(e00, cb + 16, q2, aB0); efrag(e10, cb + 16, q2, aB1); }
        } else {   // XMODE == 2: dir group, aA only
#pragma unroll
            for (int r = 0; r < 4; r++) { aA0[r] = xd0[r]; aA1[r] = xd1[r]; }
        }
        const u32 ga = base + (u32)g * 64u;

        if (XMODE == 0) {
            u32 V[2][4][4];
#pragma unroll
            for (int t = 0; t < 4; t++) lds128(V[0][t], ga + (u32)t * (8u * (u32)STB));
#pragma unroll
            for (int h = 0; h < H; h++) {
                if (h + 1 < H) {
#pragma unroll
                    for (int t = 0; t < 4; t++)
                        lds128(V[(h+1)&1][t], ga + (u32)(4*(h+1)+t) * (8u * (u32)STB));
                }
                const u32 (*v)[4] = V[h&1];
#pragma unroll
                for (int t = 0; t < 4; t++) {
                    mma16816(C0[4*h+t], aA0, v[t][0], v[t][1]);
                    mma16816(C1[4*h+t], aA1, v[t][0], v[t][1]);
                }
#pragma unroll
                for (int t = 0; t < 4; t++) {
                    mma16816(C0[4*h+t], aB0, v[t][2], v[t][3]);
                    mma16816(C1[4*h+t], aB1, v[t][2], v[t][3]);
                }
            }
        } else {
#pragma unroll
            for (int h = 0; h < H; h++) {
                u32 V[4][4];
#pragma unroll
                for (int t = 0; t < 4; t++)
                    lds128(V[t], ga + (u32)(4*h+t) * (8u * (u32)STB));
#pragma unroll
                for (int t = 0; t < 4; t++) {
                    mma16816(C0[4*h+t], aA0, V[t][0], V[t][1]);
                    mma16816(C1[4*h+t], aA1, V[t][0], V[t][1]);
                }
                if (haveB) {
#pragma unroll
                    for (int t = 0; t < 4; t++) {
                        mma16816(C0[4*h+t], aB0, V[t][2], V[t][3]);
                        mma16816(C1[4*h+t], aB1, V[t][2], V[t][3]);
                    }
                }
            }
        }
    }
}

// packed epilogue: C -> f16x2 pairs, + f16x2 bias, (relu), straight into AF
template <bool RELU>
__device__ __forceinline__ void epi_std(float (&C)[16][4], u32 (&AF)[8][4],
                                        const u32* bh, int q)
{
#pragma unroll
    for (int kf = 0; kf < 8; kf++) {
        u32 bA = bh[8 * kf + q];
        u32 bB = bh[8 * kf + 4 + q];
        u32 c0 = hadd2(pkh(C[2*kf][0],   C[2*kf][1]),   bA);
        u32 c1 = hadd2(pkh(C[2*kf][2],   C[2*kf][3]),   bA);
        u32 c2 = hadd2(pkh(C[2*kf+1][0], C[2*kf+1][1]), bB);
        u32 c3 = hadd2(pkh(C[2*kf+1][2], C[2*kf+1][3]), bB);
        if (RELU) { c0 = hmax2z(c0); c1 = hmax2z(c1); c2 = hmax2z(c2); c3 = hmax2z(c3); }
        AF[kf][0] = c0; AF[kf][1] = c1; AF[kf][2] = c2; AF[kf][3] = c3;
    }
}

// L5 epilogue with fused density head (fp32 path, fp32 bias)
__device__ __forceinline__ void epi_dens(float (&C)[16][4], u32 (&AF)[8][4],
                                         const float* bias, const float* wcS,
                                         float bd0, float* out, long long base,
                                         int q2, int q, int r0)
{
    float d0 = 0.f, d1 = 0.f;
#pragma unroll
    for (int kf = 0; kf < 8; kf++) {
        float2 bA = *(const float2*)(bias + 16 * kf + q2);
        float2 bB = *(const float2*)(bias + 16 * kf + 8 + q2);
        float2 wA = *(const float2*)(wcS + 16 * kf + q2);
        float2 wB = *(const float2*)(wcS + 16 * kf + 8 + q2);
        float f0 = fmaxf(C[2*kf][0] + bA.x, 0.f), f1 = fmaxf(C[2*kf][1] + bA.y, 0.f);
        float f2 = fmaxf(C[2*kf][2] + bA.x, 0.f), f3 = fmaxf(C[2*kf][3] + bA.y, 0.f);
        float g0 = fmaxf(C[2*kf+1][0] + bB.x, 0.f), g1 = fmaxf(C[2*kf+1][1] + bB.y, 0.f);
        float g2 = fmaxf(C[2*kf+1][2] + bB.x, 0.f), g3 = fmaxf(C[2*kf+1][3] + bB.y, 0.f);
        d0 += f0 * wA.x + f1 * wA.y + g0 * wB.x + g1 * wB.y;
        d1 += f2 * wA.x + f3 * wA.y + g2 * wB.x + g3 * wB.y;
        AF[kf][0] = pkh(f0, f1); AF[kf][1] = pkh(f2, f3);
        AF[kf][2] = pkh(g0, g1); AF[kf][3] = pkh(g2, g3);
    }
    d0 += __shfl_xor_sync(0xffffffffu, d0, 1); d0 += __shfl_xor_sync(0xffffffffu, d0, 2);
    d1 += __shfl_xor_sync(0xffffffffu, d1, 1); d1 += __shfl_xor_sync(0xffffffffu, d1, 2);
    if (q == 0) {
        out[base + r0]     = fmaxf(d0 + bd0, 0.f);
        out[base + r0 + 8] = fmaxf(d1 + bd0, 0.f);
    }
}

// L7 epilogue: relu + rgb head (wr2 + sigmoid) — fp32 path
__device__ __forceinline__ void epi_rgb(float (&C)[16][4], const float* bias,
                                        const float* wr2S, const float* br2S,
                                        float* out, long long obase,
                                        int q2, int q, int r0)
{
    float p00 = 0.f, p01 = 0.f, p02 = 0.f, p10 = 0.f, p11 = 0.f, p12 = 0.f;
#pragma unroll
    for (int nt = 0; nt < 8; nt++) {
        float2 b = *(const float2*)(bias + 8 * nt + q2);
        float f0 = fmaxf(C[nt][0] + b.x, 0.f), f1 = fmaxf(C[nt][1] + b.y, 0.f);
        float f2 = fmaxf(C[nt][2] + b.x, 0.f), f3 = fmaxf(C[nt][3] + b.y, 0.f);
        int p0 = 8 * nt + q2;
        const float* wA = wr2S + p0 * 3;
        const float* wB = wr2S + (p0 + 1) * 3;
        p00 += f0 * wA[0] + f1 * wB[0];
        p01 += f0 * wA[1] + f1 * wB[1];
        p02 += f0 * wA[2] + f1 * wB[2];
        p10 += f2 * wA[0] + f3 * wB[0];
        p11 += f2 * wA[1] + f3 * wB[1];
        p12 += f2 * wA[2] + f3 * wB[2];
    }
    p00 += __shfl_xor_sync(0xffffffffu, p00, 1); p00 += __shfl_xor_sync(0xffffffffu, p00, 2);
    p01 += __shfl_xor_sync(0xffffffffu, p01, 1); p01 += __shfl_xor_sync(0xffffffffu, p01, 2);
    p02 += __shfl_xor_sync(0xffffffffu, p02, 1); p02 += __shfl_xor_sync(0xffffffffu, p02, 2);
    p10 += __shfl_xor_sync(0xffffffffu, p10, 1); p10 += __shfl_xor_sync(0xffffffffu, p10, 2);
    p11 += __shfl_xor_sync(0xffffffffu, p11, 1); p11 += __shfl_xor_sync(0xffffffffu, p11, 2);
    p12 += __shfl_xor_sync(0xffffffffu, p12, 1); p12 += __shfl_xor_sync(0xffffffffu, p12, 2);
    if (q == 0) {
        long long o0 = obase + (long long)r0 * 3;
        long long o1 = obase + (long long)(r0 + 8) * 3;
        out[o0]     = 1.f / (1.f + __expf(-(p00 + br2S[0])));
        out[o0 + 1] = 1.f / (1.f + __expf(-(p01 + br2S[1])));
        out[o0 + 2] = 1.f / (1.f + __expf(-(p02 + br2S[2])));
        out[o1]     = 1.f / (1.f + __expf(-(p10 + br2S[0])));
        out[o1 + 1] = 1.f / (1.f + __expf(-(p11 + br2S[1])));
        out[o1 + 2] = 1.f / (1.f + __expf(-(p12 + br2S[2])));
    }
}

// ---- prep: fp32 W[k][n] -> f16 Wt[n][pos], 32-slot quad-interleaved layout ----
__global__ void prep_kernel(const float* w0, const float* w1, const float* w2, const float* w3,
                            const float* w4, const float* w5, const float* wd, const float* wr1)
{
    const float* srcs[8] = {w0, w1, w2, w3, w4, w5, wd, wr1};
    const int Ksrc[8] = {39, 128, 128, 167, 128, 128, 128, 143};
    const int Kslt[8] = {64, 128, 128, 192, 128, 128, 128, 160};
    const int Nn[8]   = {128, 128, 128, 128, 128, 128, 128, 64};
    const int STw[8]  = {96, 160, 160, 224, 160, 160, 160, 160};
    const int wst[8]  = {128, 128, 128, 128, 128, 128, 129, 64};
    const int cof[8]  = {0, 0, 0, 0, 0, 0, 1, 0};
    const int off[8]  = {0, 24576, 65536, 106496, 163840, 204800, 245760, 286720};
    int j = blockIdx.x;
    const float* src = srcs[j];
    int N = Nn[j], S = STw[j], KS = Kslt[j], tot = N * KS;
    u16* img = (u16*)(g_wimg + off[j]);
    for (int idx = threadIdx.x; idx < tot; idx += blockDim.x) {
        int n = idx / KS, s = idx - n * KS;
        float v = (s < Ksrc[j]) ? __ldg(src + (size_t)s * wst[j] + cof[j] + n) : 0.f;
        int u = s & 31, g32 = s >> 5;
        int q = (u & 7) >> 1;
        int pos = g32 * 32 + q * 8 + ((u >> 4) & 1) * 4 + ((u >> 3) & 1) * 2 + (u & 1);
        img[(size_t)n * S + pos] = __half_as_ushort(__float2half_rn(v));
    }
}

__global__ void __launch_bounds__(NTHR, 1) nerf_mma_kernel(
    const float* __restrict__ pts, const float* __restrict__ dirs,
    const float* __restrict__ b0, const float* __restrict__ b1,
    const float* __restrict__ b2, const float* __restrict__ b3,
    const float* __restrict__ b4, const float* __restrict__ b5,
    const float* __restrict__ bd, const float* __restrict__ br1,
    const float* __restrict__ wd, const float* __restrict__ wr2,
    const float* __restrict__ br2, float* __restrict__ out, int ntiles)
{
    extern __shared__ __align__(16) unsigned char sm[];
    unsigned char* wbuf0 = sm;                       // 69632  (even layers)
    unsigned char* wbuf1 = sm + 69632;               // 94208  (odd layers, incl L3)
    float* esm  = (float*)(sm + 163840);             // 256 x ES fp32 embed (2 tiles)
    float* aux  = (float*)(sm + 163840 + 256 * ES * 4);
    float* biasS = aux;                              // 8 x 128 fp32 (for dens/rgb epi)
    float* wcS   = aux + 1024;                       // wd col 0
    float* wr2S  = aux + 1152;                       // 64 x 3
    float* br2S  = aux + 1344;                       // 3
    u32*  biasH  = (u32*)(aux + 1348);               // 8 x 64 f16x2-packed biases
    const u32 wb0 = smaddr(wbuf0), wb1 = smaddr(wbuf1);

    const int tid = threadIdx.x, lane = tid & 31, wid = tid >> 5;
    const int q  = lane & 3;
    const int q2 = 2 * q;
    const int r0 = 16 * wid + (lane >> 2);
    const int nl = lane >> 2;

    {
        const float* bp[8] = {b0, b1, b2, b3, b4, b5, bd + 1, br1};
#pragma unroll 1
        for (int l = 0; l < 8; l++) {
            int n = (l == 7) ? 64 : 128;
            for (int i = tid; i < n; i += NTHR) biasS[l * 128 + i] = __ldg(bp[l] + i);
        }
        for (int i = tid; i < 128; i += NTHR) wcS[i] = __ldg(wd + (size_t)i * 129);
        for (int i = tid; i < 192; i += NTHR) wr2S[i] = __ldg(wr2 + i);
        if (tid < 3) br2S[tid] = __ldg(br2 + tid);
        // pack biases to f16x2: biasH[l*64 + kf*8 + half*4 + qq]
        for (int i = tid; i < 512; i += NTHR) {
            int l = i >> 6, rem = i & 63;
            int kf = rem >> 3, half = (rem >> 2) & 1, qq = rem & 3;
            int n0 = 16 * kf + 8 * half + 2 * qq;
            float v0 = 0.f, v1 = 0.f;
            int lim = (l == 7) ? 64 : 128;
            if (n0 < lim)     v0 = __ldg(bp[l] + n0);
            if (n0 + 1 < lim) v1 = __ldg(bp[l] + n0 + 1);
            biasH[i] = pkh(v0, v1);
        }
    }
    copy_async(wb0, g_wimg, 24576, tid);   // L0
    CPW();
    __syncthreads();

    float C0[16][4], C1[16][4];
    u32 AF0[8][4], AF1[8][4];
    const float bd0 = __ldg(bd);
    const long long NPTS = (long long)ntiles * 128;
    const int npairs = ntiles >> 1;

    const u32 t192 = (u32)(nl * 192 + q * 16);
    const u32 t320 = (u32)(nl * 320 + q * 16);
    const u32 t448 = (u32)(nl * 448 + q * 16);
    const float* e00 = esm + r0 * ES;
    const float* e10 = esm + (128 + r0) * ES;

    for (int pair = blockIdx.x; pair < npairs; pair += gridDim.x) {
        // ---- xyz harmonic embed for BOTH tiles (2 threads per point, 2 passes) ----
#pragma unroll 1
        for (int p2 = 0; p2 < 2; p2++) {
            int p = tid & 127, half = tid >> 7;
            const float* qp = pts + (((long long)(2 * pair + p2)) * 128 + p) * 3;
            float v0 = __ldg(qp), v1 = __ldg(qp + 1), v2 = __ldg(qp + 2);
            float* er = esm + (p2 * 128 + p) * ES;
            if (half == 0) {
                float fr = 1.f;
#pragma unroll
                for (int f = 0; f < 6; f++) {
                    float s, c; fsincos(v0 * fr, &s, &c);
                    er[f] = s; er[18 + f] = c; fr *= 2.f;
                }
                fr = 1.f;
#pragma unroll
                for (int f = 0; f < 3; f++) {
                    float s, c; fsincos(v2 * fr, &s, &c);
                    er[12 + f] = s; er[30 + f] = c; fr *= 2.f;
                }
                er[36] = v0; er[37] = v1; er[38] = v2;
#pragma unroll
                for (int i = 39; i < 48; i++) er[i] = 0.f;
            } else {
                float fr = 1.f;
#pragma unroll
                for (int f = 0; f < 6; f++) {
                    float s, c; fsincos(v1 * fr, &s, &c);
                    er[6 + f] = s; er[24 + f] = c; fr *= 2.f;
                }
                fr = 8.f;
#pragma unroll
                for (int f = 3; f < 6; f++) {
                    float s, c; fsincos(v2 * fr, &s, &c);
                    er[12 + f] = s; er[30 + f] = c; fr *= 2.f;
                }
            }
        }
        __syncthreads();

        // ---- L0 (xyz from esm, 2 extra groups, last kf skipped) ----
        copy_async(wb1, g_wimg + 24576, 40960, tid);
        gemm_dual<0, 1, 16, 192>(C0, C1, AF0, AF1, wb0 + t192, e00, e10, 0, 0, q2);
        epi_std<true>(C0, AF0, biasH, q);
        epi_std<true>(C1, AF1, biasH, q);
        CPW(); __syncthreads();

        // ---- L1 ----
        copy_async(wb0, g_wimg + 65536, 40960, tid);
        gemm_dual<4, 0, 16, 320>(C0, C1, AF0, AF1, wb1 + t320, 0, 0, 0, 0, q2);
        epi_std<true>(C0, AF0, biasH + 64, q);
        epi_std<true>(C1, AF1, biasH + 64, q);
        CPW(); __syncthreads();

        // ---- L2 ----
        copy_async(wb1, g_wimg + 106496, 57344, tid);
        gemm_dual<4, 0, 16, 320>(C0, C1, AF0, AF1, wb0 + t320, 0, 0, 0, 0, q2);
        epi_std<true>(C0, AF0, biasH + 128, q);
        epi_std<true>(C1, AF1, biasH + 128, q);
        CPW(); __syncthreads();

        // ---- L3 (skip concat: 4 AF groups + 2 esm groups) ----
        copy_async(wb0, g_wimg + 163840, 40960, tid);
        gemm_dual<4, 1, 16, 448>(C0, C1, AF0, AF1, wb1 + t448, e00, e10, 0, 0, q2);
        epi_std<true>(C0, AF0, biasH + 192, q);
        epi_std<true>(C1, AF1, biasH + 192, q);
        CPW(); __syncthreads();

        // ---- L4 ----
        copy_async(wb1, g_wimg + 204800, 40960, tid);
        gemm_dual<4, 0, 16, 320>(C0, C1, AF0, AF1, wb0 + t320, 0, 0, 0, 0, q2);
        epi_std<true>(C0, AF0, biasH + 256, q);
        epi_std<true>(C1, AF1, biasH + 256, q);
        CPW(); __syncthreads();

        // ---- L5 (+fused density heads, fp32 epilogue) ----
        copy_async(wb0, g_wimg + 245760, 40960, tid);
        gemm_dual<4, 0, 16, 320>(C0, C1, AF0, AF1, wb1 + t320, 0, 0, 0, 0, q2);
        {
            long long base0 = (long long)(2 * pair) * 128;
            epi_dens(C0, AF0, biasS + 640, wcS, bd0, out, base0,       q2, q, r0);
            epi_dens(C1, AF1, biasS + 640, wcS, bd0, out, base0 + 128, q2, q, r0);
        }
        CPW(); __syncthreads();

        // ---- L6 (wd cols 1..128, NO relu) ----
        copy_async(wb1, g_wimg + 286720, 20480, tid);
        gemm_dual<4, 0, 16, 320>(C0, C1, AF0, AF1, wb0 + t320, 0, 0, 0, 0, q2);
        epi_std<false>(C0, AF0, biasH + 384, q);
        epi_std<false>(C1, AF1, biasH + 384, q);
        CPW(); __syncthreads();

        // ---- dir frags for both tiles (4 regs each) ----
        u32 xd0[4], xd1[4];
#pragma unroll 1
        for (int p2 = 0; p2 < 2; p2++) {
            const float* dp = dirs + (long long)(2 * pair + p2) * 3;
            float d[16];
#pragma unroll
            for (int c = 0; c < 3; c++) {
                float v = __ldg(dp + c);
                float s0, cc0, s1, cc1;
                fsincos(v, &s0, &cc0); fsincos(2.f * v, &s1, &cc1);
                d[2*c] = s0; d[2*c+1] = s1; d[6+2*c] = cc0; d[7+2*c] = cc1; d[12+c] = v;
            }
            d[15] = 0.f;
            u32 lo = pkh(d[q2], d[q2+1]);
            u32 hi = pkh(d[8+q2], d[9+q2]);
            u32* xd = (p2 == 0) ? xd0 : xd1;
            xd[0] = lo; xd[1] = lo; xd[2] = hi; xd[3] = hi;
        }

        // ---- L7 (wr1 -> 64: 4 AF groups + dir group (aA only), +fused rgb heads) ----
        copy_async(wb0, g_wimg, 24576, tid);   // next pair's L0
        gemm_dual<4, 2, 8, 320>(C0, C1, AF0, AF1, wb1 + t320, 0, 0, xd0, xd1, q2);
        {
            long long pb0 = (long long)(2 * pair) * 128;
            epi_rgb(C0, biasS + 896, wr2S, br2S, out, NPTS + pb0 * 3,         q2, q, r0);
            epi_rgb(C1, biasS + 896, wr2S, br2S, out, NPTS + (pb0 + 128) * 3, q2, q, r0);
        }
        CPW(); __syncthreads();
    }
}

extern "C" void kernel_launch(void* const* d_in, const int* in_sizes, int n_in,
                              void* d_out, int out_size)
{
    const float* pts  = (const float*)d_in[0];
    const float* dirs = (const float*)d_in[1];
    const float *w0 = (const float*)d_in[2],  *b0 = (const float*)d_in[3];
    const float *w1 = (const float*)d_in[4],  *b1 = (const float*)d_in[5];
    const float *w2 = (const float*)d_in[6],  *b2 = (const float*)d_in[7];
    const float *w3 = (const float*)d_in[8],  *b3 = (const float*)d_in[9];
    const float *w4 = (const float*)d_in[10], *b4 = (const float*)d_in[11];
    const float *w5 = (const float*)d_in[12], *b5 = (const float*)d_in[13];
    const float *wd = (const float*)d_in[14], *bd = (const float*)d_in[15];
    const float *wr1 = (const float*)d_in[16], *br1 = (const float*)d_in[17];
    const float *wr2 = (const float*)d_in[18], *br2 = (const float*)d_in[19];
    float* out = (float*)d_out;

    int ntiles = in_sizes[1] / 3;   // rays
    int npairs = ntiles >> 1;
    int nsm = 0;
    cudaDeviceGetAttribute(&nsm, cudaDevAttrMultiProcessorCount, 0);
    if (nsm <= 0) nsm = 148;
    int grid = nsm < npairs ? nsm : npairs;

    size_t smem = 163840 + 256 * ES * 4 + 7440;   // 224528
    cudaFuncSetAttribute(nerf_mma_kernel, cudaFuncAttributeMaxDynamicSharedMemorySize, (int)smem);

    prep_kernel<<<8, 512>>>(w0, w1, w2, w3, w4, w5, wd, wr1);
    nerf_mma_kernel<<<grid, NTHR, smem>>>(pts, dirs, b0, b1, b2, b3, b4, b5,
                                          bd, br1, wd, wr2, br2, out, ntiles);
}